// round 2
// baseline (speedup 1.0000x reference)
#include <cuda_runtime.h>
#include <cuda_bf16.h>
#include <cstdint>

#define CU_T 8192
#define CU_K 2048
#define CU_N 2048
#define CU_E 8

#define BM 128
#define BN 128
#define BK 32
#define KTILES (CU_K / BK)      // 64
#define NSTAGE 4
#define STAGE_BYTES 32768       // Ah(8K)+Al(8K)+Bh(8K)+Bl(8K)
#define SM_TOK 0                // 128 ints
#define SM_TILES 1024
#define SM_TOTAL (SM_TILES + NSTAGE * STAGE_BYTES)   // 132096

// ---------------- scratch (static device globals; no allocation) ----------------
__device__ __nv_bfloat16 g_Ahi[(size_t)CU_T * CU_K];
__device__ __nv_bfloat16 g_Alo[(size_t)CU_T * CU_K];
__device__ __nv_bfloat16 g_Bhi[(size_t)CU_E * CU_N * CU_K];   // [e][n][k] K-major
__device__ __nv_bfloat16 g_Blo[(size_t)CU_E * CU_N * CU_K];
__device__ int g_cnt[CU_E];
__device__ int g_off[CU_E];
__device__ int g_cur[CU_E];
__device__ int g_idx[CU_T];

// ---------------- PTX helpers ----------------
__device__ __forceinline__ uint32_t smem_u32(const void* p) {
    uint32_t a;
    asm("{ .reg .u64 t; cvta.to.shared.u64 t, %1; cvt.u32.u64 %0, t; }"
        : "=r"(a) : "l"(p));
    return a;
}

__device__ __forceinline__ void cp_async16(uint32_t dst, const void* src) {
    asm volatile("cp.async.cg.shared.global [%0], [%1], 16;" :: "r"(dst), "l"(src));
}
#define CP_COMMIT() asm volatile("cp.async.commit_group;" ::: "memory")
#define CP_WAIT2()  asm volatile("cp.async.wait_group 2;" ::: "memory")

__device__ __forceinline__ void ldsm4(uint32_t* r, uint32_t addr) {
    asm volatile("ldmatrix.sync.aligned.m8n8.x4.shared.b16 {%0,%1,%2,%3}, [%4];"
                 : "=r"(r[0]), "=r"(r[1]), "=r"(r[2]), "=r"(r[3]) : "r"(addr));
}

__device__ __forceinline__ void mma16816(float* d, const uint32_t* a, const uint32_t* b) {
    asm volatile(
        "mma.sync.aligned.m16n8k16.row.col.f32.bf16.bf16.f32 "
        "{%0,%1,%2,%3}, {%4,%5,%6,%7}, {%8,%9}, {%0,%1,%2,%3};"
        : "+f"(d[0]), "+f"(d[1]), "+f"(d[2]), "+f"(d[3])
        : "r"(a[0]), "r"(a[1]), "r"(a[2]), "r"(a[3]), "r"(b[0]), "r"(b[1]));
}

// swizzled byte offset inside one 128x32 bf16 tile (64B rows, 16B chunks)
__device__ __forceinline__ uint32_t swz(int row, int chunk) {
    return (uint32_t)(row * 64 + ((chunk ^ ((row >> 1) & 3)) << 4));
}

// ---------------- prep kernels ----------------
__global__ void __launch_bounds__(256) k_cvt_tok(const float* __restrict__ x) {
    size_t i = ((size_t)blockIdx.x * 256 + threadIdx.x) * 8;
    float4 a = *(const float4*)(x + i);
    float4 b = *(const float4*)(x + i + 4);
    float v[8] = {a.x, a.y, a.z, a.w, b.x, b.y, b.z, b.w};
    __align__(16) __nv_bfloat16 h[8];
    __align__(16) __nv_bfloat16 l[8];
#pragma unroll
    for (int j = 0; j < 8; ++j) {
        h[j] = __float2bfloat16(v[j]);
        l[j] = __float2bfloat16(v[j] - __bfloat162float(h[j]));
    }
    *(uint4*)(g_Ahi + i) = *(uint4*)h;
    *(uint4*)(g_Alo + i) = *(uint4*)l;
}

// weight [E][K][N] fp32 -> g_B{hi,lo} [E][N][K] bf16 (transpose + split)
__global__ void __launch_bounds__(256) k_cvt_w(const float* __restrict__ w) {
    __shared__ float s[64][65];
    const int e = blockIdx.z;
    const int k0 = blockIdx.y * 64;
    const int n0 = blockIdx.x * 64;
    const int tid = threadIdx.x;
#pragma unroll
    for (int i = 0; i < 4; ++i) {
        int task = tid + i * 256;            // 1024 tasks: 64 k-rows x 16 float4
        int kr = task >> 4;
        int nc = (task & 15) * 4;
        float4 v = *(const float4*)(w + ((size_t)e * CU_K + k0 + kr) * CU_N + n0 + nc);
        s[kr][nc + 0] = v.x; s[kr][nc + 1] = v.y;
        s[kr][nc + 2] = v.z; s[kr][nc + 3] = v.w;
    }
    __syncthreads();
#pragma unroll
    for (int i = 0; i < 2; ++i) {
        int task = tid + i * 256;            // 512 tasks: 64 n-rows x 8 k-octets
        int nr = task >> 3;
        int j = (task & 7) * 8;
        __align__(16) __nv_bfloat16 h[8];
        __align__(16) __nv_bfloat16 l[8];
#pragma unroll
        for (int q = 0; q < 8; ++q) {
            float v = s[j + q][nr];
            h[q] = __float2bfloat16(v);
            l[q] = __float2bfloat16(v - __bfloat162float(h[q]));
        }
        size_t dst = ((size_t)e * CU_N + n0 + nr) * CU_K + k0 + j;
        *(uint4*)(g_Bhi + dst) = *(uint4*)h;
        *(uint4*)(g_Blo + dst) = *(uint4*)l;
    }
}

__global__ void k_zero() {
    if (threadIdx.x < CU_E) g_cnt[threadIdx.x] = 0;
}

__global__ void __launch_bounds__(256) k_count(const int* __restrict__ ids) {
    int t = blockIdx.x * 256 + threadIdx.x;
    if (t < CU_T) atomicAdd(&g_cnt[ids[t]], 1);
}

__global__ void k_off() {
    if (threadIdx.x == 0) {
        int s = 0;
        for (int e = 0; e < CU_E; ++e) { g_off[e] = s; g_cur[e] = s; s += g_cnt[e]; }
    }
}

__global__ void __launch_bounds__(256) k_scatter(const int* __restrict__ ids) {
    int t = blockIdx.x * 256 + threadIdx.x;
    if (t < CU_T) {
        int p = atomicAdd(&g_cur[ids[t]], 1);
        g_idx[p] = t;
    }
}

// ---------------- grouped GEMM (mma.sync bf16 hi/lo 3-pass) ----------------
__device__ __forceinline__ void issue_stage(uint32_t tiles_base, int stage, int kt,
                                            const int* __restrict__ toks,
                                            size_t bbase, int tid) {
    const int k0 = kt * BK;
    const uint32_t st = tiles_base + stage * STAGE_BYTES;
#pragma unroll
    for (int i = 0; i < 8; ++i) {
        const int task = i * 256 + tid;       // 2048 tasks = 4 mats x 128 rows x 4 chunks
        const int mat = task >> 9;
        const int t = task & 511;
        const int row = t >> 2;
        const int chunk = t & 3;
        const uint32_t dst = st + mat * 8192 + swz(row, chunk);
        const __nv_bfloat16* src;
        if (mat == 0)
            src = g_Ahi + (size_t)toks[row] * CU_K + k0 + chunk * 8;
        else if (mat == 1)
            src = g_Alo + (size_t)toks[row] * CU_K + k0 + chunk * 8;
        else if (mat == 2)
            src = g_Bhi + bbase + (size_t)row * CU_K + k0 + chunk * 8;
        else
            src = g_Blo + bbase + (size_t)row * CU_K + k0 + chunk * 8;
        cp_async16(dst, src);
    }
}

__global__ void __launch_bounds__(256, 1) moe_gemm(float* __restrict__ out) {
    const int e = blockIdx.z;
    const int cnt = g_cnt[e];
    const int m0 = blockIdx.y * BM;
    if (m0 >= cnt) return;
    const int n0 = blockIdx.x * BN;

    extern __shared__ __align__(1024) char smem[];
    const uint32_t sb = smem_u32(smem);
    const uint32_t tiles = sb + SM_TILES;
    const int tid = threadIdx.x;
    const int wid = tid >> 5;
    const int lid = tid & 31;

    int* toks_s = (int*)(smem + SM_TOK);
    if (tid < BM) {
        int lr = m0 + tid;
        toks_s[tid] = (lr < cnt) ? g_idx[g_off[e] + lr] : 0;
    }
    __syncthreads();
    const int* toks = toks_s;
    const size_t bbase = ((size_t)e * CU_N + n0) * CU_K;

    // prologue: prefetch 3 stages
#pragma unroll
    for (int s = 0; s < 3; ++s) {
        issue_stage(tiles, s, s, toks, bbase, tid);
        CP_COMMIT();
    }

    // warp / lane decomposition
    const int wm = (wid & 1) * 64;       // warp M offset in tile
    const int wn = (wid >> 1) * 32;      // warp N offset in tile
    const int q = lid >> 3;              // ldmatrix quad
    const int r = lid & 7;

    float acc[4][4][4];
#pragma unroll
    for (int mi = 0; mi < 4; ++mi)
#pragma unroll
        for (int ni = 0; ni < 4; ++ni)
#pragma unroll
            for (int c = 0; c < 4; ++c) acc[mi][ni][c] = 0.f;

    // per-thread ldmatrix row indices (chunk varies with ks)
    const int arow_base = wm + ((q & 1) << 3) + r;   // + mi*16
    const int achunk_hi = q >> 1;                    // + ks*2
    const int brow_base = wn + ((q >> 1) << 3) + r;  // + p*16
    const int bchunk_lo = q & 1;                     // + ks*2

    for (int kt = 0; kt < KTILES; ++kt) {
        CP_WAIT2();
        __syncthreads();
        if (kt + 3 < KTILES) issue_stage(tiles, (kt + 3) & 3, kt + 3, toks, bbase, tid);
        CP_COMMIT();

        const uint32_t st = tiles + (kt & 3) * STAGE_BYTES;
        const uint32_t stAh = st, stAl = st + 8192, stBh = st + 16384, stBl = st + 24576;

#pragma unroll
        for (int ks = 0; ks < 2; ++ks) {
            uint32_t ah[4][4], al[4][4], bh[2][4], bl[2][4];
#pragma unroll
            for (int mi = 0; mi < 4; ++mi) {
                const int row = arow_base + mi * 16;
                const uint32_t o = swz(row, ks * 2 + achunk_hi);
                ldsm4(ah[mi], stAh + o);
                ldsm4(al[mi], stAl + o);
            }
#pragma unroll
            for (int p = 0; p < 2; ++p) {
                const int row = brow_base + p * 16;
                const uint32_t o = swz(row, ks * 2 + bchunk_lo);
                ldsm4(bh[p], stBh + o);
                ldsm4(bl[p], stBl + o);
            }
#pragma unroll
            for (int mi = 0; mi < 4; ++mi)
#pragma unroll
                for (int ni = 0; ni < 4; ++ni) {
                    const uint32_t* bhp = &bh[ni >> 1][(ni & 1) * 2];
                    const uint32_t* blp = &bl[ni >> 1][(ni & 1) * 2];
                    mma16816(acc[mi][ni], ah[mi], bhp);
                    mma16816(acc[mi][ni], al[mi], bhp);
                    mma16816(acc[mi][ni], ah[mi], blp);
                }
        }
    }

    // epilogue: write accumulators to gathered output rows
    const int g = lid >> 2;      // groupID (row within m16)
    const int tq = lid & 3;      // col pair index
#pragma unroll
    for (int mi = 0; mi < 4; ++mi) {
        const int lr0 = wm + mi * 16 + g;
        const int lr1 = lr0 + 8;
#pragma unroll
        for (int ni = 0; ni < 4; ++ni) {
            const int col = n0 + wn + ni * 8 + tq * 2;
            if (m0 + lr0 < cnt) {
                float2 v = {acc[mi][ni][0], acc[mi][ni][1]};
                *(float2*)(out + (size_t)toks[lr0] * CU_N + col) = v;
            }
            if (m0 + lr1 < cnt) {
                float2 v = {acc[mi][ni][2], acc[mi][ni][3]};
                *(float2*)(out + (size_t)toks[lr1] * CU_N + col) = v;
            }
        }
    }
}

// ---------------- launch ----------------
extern "C" void kernel_launch(void* const* d_in, const int* in_sizes, int n_in,
                              void* d_out, int out_size) {
    const float* tokens = (const float*)d_in[0];
    const float* weight = (const float*)d_in[1];
    const int*   ids    = (const int*)d_in[2];
    float* out = (float*)d_out;

    cudaFuncSetAttribute(moe_gemm, cudaFuncAttributeMaxDynamicSharedMemorySize, SM_TOTAL);

    k_cvt_tok<<<(CU_T * CU_K) / 2048, 256>>>(tokens);
    k_cvt_w<<<dim3(CU_N / 64, CU_K / 64, CU_E), 256>>>(weight);
    k_zero<<<1, 32>>>();
    k_count<<<CU_T / 256, 256>>>(ids);
    k_off<<<1, 32>>>();
    k_scatter<<<CU_T / 256, 256>>>(ids);
    moe_gemm<<<dim3(CU_N / BN, CU_T / BM, CU_E), 256, SM_TOTAL>>>(out);
}

// round 4
// speedup vs baseline: 1.5533x; 1.5533x over previous
#include <cuda_runtime.h>
#include <cuda_fp16.h>
#include <cstdint>

#define CU_T 8192
#define CU_K 2048
#define CU_N 2048
#define CU_E 8

#define BM 128
#define BN 128
#define BK 32
#define KTILES (CU_K / BK)      // 64
#define NSTAGE 4
#define STAGE_BYTES 24576       // Ah(8K)+Al(8K)+Bh(8K)
#define SM_TOK 0                // 128 ints
#define SM_TILES 1024
#define SM_TOTAL (SM_TILES + NSTAGE * STAGE_BYTES)   // 99328 (97KB) -> 2 CTAs/SM

// ---------------- scratch (static device globals; no allocation) ----------------
__device__ __half g_Ahi[(size_t)CU_T * CU_K];
__device__ __half g_Alo[(size_t)CU_T * CU_K];
__device__ __half g_Bh[(size_t)CU_E * CU_N * CU_K];   // [e][n][k] K-major
__device__ int g_cnt[CU_E];
__device__ int g_off[CU_E];
__device__ int g_idx[CU_T];

// ---------------- PTX helpers ----------------
__device__ __forceinline__ uint32_t smem_u32(const void* p) {
    uint32_t a;
    asm("{ .reg .u64 t; cvta.to.shared.u64 t, %1; cvt.u32.u64 %0, t; }"
        : "=r"(a) : "l"(p));
    return a;
}

__device__ __forceinline__ void cp_async16(uint32_t dst, const void* src) {
    asm volatile("cp.async.cg.shared.global [%0], [%1], 16;" :: "r"(dst), "l"(src));
}
#define CP_COMMIT() asm volatile("cp.async.commit_group;" ::: "memory")
#define CP_WAIT2()  asm volatile("cp.async.wait_group 2;" ::: "memory")

__device__ __forceinline__ void ldsm4(uint32_t* r, uint32_t addr) {
    asm volatile("ldmatrix.sync.aligned.m8n8.x4.shared.b16 {%0,%1,%2,%3}, [%4];"
                 : "=r"(r[0]), "=r"(r[1]), "=r"(r[2]), "=r"(r[3]) : "r"(addr));
}

__device__ __forceinline__ void mma16816(float* d, const uint32_t* a, const uint32_t* b) {
    asm volatile(
        "mma.sync.aligned.m16n8k16.row.col.f32.f16.f16.f32 "
        "{%0,%1,%2,%3}, {%4,%5,%6,%7}, {%8,%9}, {%0,%1,%2,%3};"
        : "+f"(d[0]), "+f"(d[1]), "+f"(d[2]), "+f"(d[3])
        : "r"(a[0]), "r"(a[1]), "r"(a[2]), "r"(a[3]), "r"(b[0]), "r"(b[1]));
}

// swizzled byte offset inside one 128x32 f16 tile (64B rows, 16B chunks)
__device__ __forceinline__ uint32_t swz(int row, int chunk) {
    return (uint32_t)(row * 64 + ((chunk ^ ((row >> 1) & 3)) << 4));
}

// ---------------- prep kernels ----------------
// tokens fp32 -> A hi/lo fp16 (2-term split). Each thread handles 8 values.
__global__ void __launch_bounds__(256) k_cvt_tok(const float* __restrict__ x, int blk0) {
    size_t i = ((size_t)(blockIdx.x + blk0) * 256 + threadIdx.x) * 8;
    float4 a = *(const float4*)(x + i);
    float4 b = *(const float4*)(x + i + 4);
    float v[8] = {a.x, a.y, a.z, a.w, b.x, b.y, b.z, b.w};
    __align__(16) __half h[8];
    __align__(16) __half l[8];
#pragma unroll
    for (int j = 0; j < 8; ++j) {
        h[j] = __float2half_rn(v[j]);
        l[j] = __float2half_rn(v[j] - __half2float(h[j]));
    }
    *(uint4*)(g_Ahi + i) = *(uint4*)h;
    *(uint4*)(g_Alo + i) = *(uint4*)l;
}

// weight [E][K][N] fp32 -> g_Bh [E][N][K] fp16 (transpose + convert)
__global__ void __launch_bounds__(256) k_cvt_w(const float* __restrict__ w, int ebase) {
    __shared__ float s[64][65];
    const int e = blockIdx.z + ebase;
    const int k0 = blockIdx.y * 64;
    const int n0 = blockIdx.x * 64;
    const int tid = threadIdx.x;
#pragma unroll
    for (int i = 0; i < 4; ++i) {
        int task = tid + i * 256;            // 1024 tasks: 64 k-rows x 16 float4
        int kr = task >> 4;
        int nc = (task & 15) * 4;
        float4 v = *(const float4*)(w + ((size_t)e * CU_K + k0 + kr) * CU_N + n0 + nc);
        s[kr][nc + 0] = v.x; s[kr][nc + 1] = v.y;
        s[kr][nc + 2] = v.z; s[kr][nc + 3] = v.w;
    }
    __syncthreads();
#pragma unroll
    for (int i = 0; i < 2; ++i) {
        int task = tid + i * 256;            // 512 tasks: 64 n-rows x 8 k-octets
        int nr = task >> 3;
        int j = (task & 7) * 8;
        __align__(16) __half h[8];
#pragma unroll
        for (int q = 0; q < 8; ++q) h[q] = __float2half_rn(s[j + q][nr]);
        size_t dst = ((size_t)e * CU_N + n0 + nr) * CU_K + k0 + j;
        *(uint4*)(g_Bh + dst) = *(uint4*)h;
    }
}

// fused histogram + prefix + scatter (single CTA)
__global__ void __launch_bounds__(1024) k_bucket(const int* __restrict__ ids) {
    __shared__ int cnt[CU_E], cur[CU_E];
    const int tid = threadIdx.x;
    if (tid < CU_E) cnt[tid] = 0;
    __syncthreads();
#pragma unroll
    for (int i = 0; i < CU_T / 1024; ++i)
        atomicAdd(&cnt[ids[tid + i * 1024]], 1);
    __syncthreads();
    if (tid == 0) {
        int s = 0;
        for (int e = 0; e < CU_E; ++e) {
            g_cnt[e] = cnt[e];
            g_off[e] = s;
            cur[e] = s;
            s += cnt[e];
        }
    }
    __syncthreads();
#pragma unroll
    for (int i = 0; i < CU_T / 1024; ++i) {
        int t = tid + i * 1024;
        int p = atomicAdd(&cur[ids[t]], 1);
        g_idx[p] = t;
    }
}

// ---------------- grouped GEMM (mma.sync fp16 A-hi/lo 2-pass) ----------------
__device__ __forceinline__ void issue_stage(uint32_t tiles_base, int stage, int kt,
                                            const int* __restrict__ toks,
                                            size_t bbase, int tid) {
    const int k0 = kt * BK;
    const uint32_t st = tiles_base + stage * STAGE_BYTES;
#pragma unroll
    for (int i = 0; i < 6; ++i) {
        const int task = i * 256 + tid;       // 1536 tasks = 3 mats x 128 rows x 4 chunks
        const int mat = task >> 9;
        const int t = task & 511;
        const int row = t >> 2;
        const int chunk = t & 3;
        const uint32_t dst = st + mat * 8192 + swz(row, chunk);
        const __half* src;
        if (mat == 0)
            src = g_Ahi + (size_t)toks[row] * CU_K + k0 + chunk * 8;
        else if (mat == 1)
            src = g_Alo + (size_t)toks[row] * CU_K + k0 + chunk * 8;
        else
            src = g_Bh + bbase + (size_t)row * CU_K + k0 + chunk * 8;
        cp_async16(dst, src);
    }
}

__global__ void __launch_bounds__(256, 2) moe_gemm(float* __restrict__ out) {
    const int e = blockIdx.z;
    const int cnt = g_cnt[e];
    const int m0 = blockIdx.y * BM;
    if (m0 >= cnt) return;
    const int n0 = blockIdx.x * BN;

    extern __shared__ __align__(1024) char smem[];
    const uint32_t sb = smem_u32(smem);
    const uint32_t tiles = sb + SM_TILES;
    const int tid = threadIdx.x;
    const int wid = tid >> 5;
    const int lid = tid & 31;

    int* toks_s = (int*)(smem + SM_TOK);
    if (tid < BM) {
        int lr = m0 + tid;
        toks_s[tid] = (lr < cnt) ? g_idx[g_off[e] + lr] : 0;
    }
    __syncthreads();
    const int* toks = toks_s;
    const size_t bbase = ((size_t)e * CU_N + n0) * CU_K;

    // prologue: prefetch 3 stages
#pragma unroll
    for (int s = 0; s < 3; ++s) {
        issue_stage(tiles, s, s, toks, bbase, tid);
        CP_COMMIT();
    }

    // warp / lane decomposition: warp tile 64x32
    const int wm = (wid & 1) * 64;
    const int wn = (wid >> 1) * 32;
    const int q = lid >> 3;
    const int r = lid & 7;

    float acc[4][4][4];
#pragma unroll
    for (int mi = 0; mi < 4; ++mi)
#pragma unroll
        for (int ni = 0; ni < 4; ++ni)
#pragma unroll
            for (int c = 0; c < 4; ++c) acc[mi][ni][c] = 0.f;

    const int arow_base = wm + ((q & 1) << 3) + r;   // + mi*16
    const int achunk_hi = q >> 1;                    // + ks*2
    const int brow_base = wn + ((q >> 1) << 3) + r;  // + p*16
    const int bchunk_lo = q & 1;                     // + ks*2

    for (int kt = 0; kt < KTILES; ++kt) {
        CP_WAIT2();
        __syncthreads();
        if (kt + 3 < KTILES) issue_stage(tiles, (kt + 3) & 3, kt + 3, toks, bbase, tid);
        CP_COMMIT();

        const uint32_t st = tiles + (kt & 3) * STAGE_BYTES;
        const uint32_t stAh = st, stAl = st + 8192, stBh = st + 16384;

#pragma unroll
        for (int ks = 0; ks < 2; ++ks) {
            uint32_t ah[4][4], al[4][4], bh[2][4];
#pragma unroll
            for (int mi = 0; mi < 4; ++mi) {
                const int row = arow_base + mi * 16;
                const uint32_t o = swz(row, ks * 2 + achunk_hi);
                ldsm4(ah[mi], stAh + o);
                ldsm4(al[mi], stAl + o);
            }
#pragma unroll
            for (int p = 0; p < 2; ++p) {
                const int row = brow_base + p * 16;
                const uint32_t o = swz(row, ks * 2 + bchunk_lo);
                ldsm4(bh[p], stBh + o);
            }
#pragma unroll
            for (int mi = 0; mi < 4; ++mi)
#pragma unroll
                for (int ni = 0; ni < 4; ++ni) {
                    const uint32_t* bhp = &bh[ni >> 1][(ni & 1) * 2];
                    mma16816(acc[mi][ni], ah[mi], bhp);
                    mma16816(acc[mi][ni], al[mi], bhp);
                }
        }
    }

    // epilogue: write accumulators to gathered output rows
    const int g = lid >> 2;
    const int tq = lid & 3;
#pragma unroll
    for (int mi = 0; mi < 4; ++mi) {
        const int lr0 = wm + mi * 16 + g;
        const int lr1 = lr0 + 8;
#pragma unroll
        for (int ni = 0; ni < 4; ++ni) {
            const int col = n0 + wn + ni * 8 + tq * 2;
            if (m0 + lr0 < cnt) {
                float2 v = {acc[mi][ni][0], acc[mi][ni][1]};
                *(float2*)(out + (size_t)toks[lr0] * CU_N + col) = v;
            }
            if (m0 + lr1 < cnt) {
                float2 v = {acc[mi][ni][2], acc[mi][ni][3]};
                *(float2*)(out + (size_t)toks[lr1] * CU_N + col) = v;
            }
        }
    }
}

// ---------------- launch ----------------
extern "C" void kernel_launch(void* const* d_in, const int* in_sizes, int n_in,
                              void* d_out, int out_size) {
    const float* tokens = (const float*)d_in[0];
    const float* weight = (const float*)d_in[1];
    const int*   ids    = (const int*)d_in[2];
    float* out = (float*)d_out;

    cudaFuncSetAttribute(moe_gemm, cudaFuncAttributeMaxDynamicSharedMemorySize, SM_TOTAL);

    const int tok_blocks = (CU_T * CU_K) / 2048;     // 8192
    // 6 launches; moe_gemm is launch index 5 so ncu -s 5 -c 1 captures it
    k_cvt_tok<<<tok_blocks / 2, 256>>>(tokens, 0);
    k_cvt_tok<<<tok_blocks / 2, 256>>>(tokens, tok_blocks / 2);
    k_cvt_w<<<dim3(CU_N / 64, CU_K / 64, CU_E / 2), 256>>>(weight, 0);
    k_cvt_w<<<dim3(CU_N / 64, CU_K / 64, CU_E / 2), 256>>>(weight, CU_E / 2);
    k_bucket<<<1, 1024>>>(ids);
    moe_gemm<<<dim3(CU_N / BN, CU_T / BM, CU_E), 256, SM_TOTAL>>>(out);
}

// round 10
// speedup vs baseline: 2.6345x; 1.6960x over previous
#include <cuda_runtime.h>
#include <cuda_fp16.h>
#include <cstdint>

#define CU_T 8192
#define CU_K 2048
#define CU_N 2048
#define CU_E 8

#define BM 128
#define BN 128
#define BK 32
#define KTILES (CU_K / BK)      // 64
#define NSTAGE 6
#define STAGE_BYTES 16384       // Ah(8K)+Bh(8K)
#define SM_TOK 0                // 128 ints
#define SM_TILES 1024
#define SM_TOTAL (SM_TILES + NSTAGE * STAGE_BYTES)   // 99328 (97KB) -> 2 CTAs/SM

// ---------------- scratch (static device globals; no allocation) ----------------
__device__ __half g_Ah[(size_t)CU_T * CU_K];
__device__ __half g_Bh[(size_t)CU_E * CU_N * CU_K];   // [e][n][k] K-major
__device__ int g_cnt[CU_E];
__device__ int g_off[CU_E];
__device__ int g_idx[CU_T];

// ---------------- PTX helpers ----------------
__device__ __forceinline__ uint32_t smem_u32(const void* p) {
    uint32_t a;
    asm("{ .reg .u64 t; cvta.to.shared.u64 t, %1; cvt.u32.u64 %0, t; }"
        : "=r"(a) : "l"(p));
    return a;
}

__device__ __forceinline__ void cp_async16(uint32_t dst, const void* src) {
    asm volatile("cp.async.cg.shared.global [%0], [%1], 16;" :: "r"(dst), "l"(src));
}
#define CP_COMMIT() asm volatile("cp.async.commit_group;" ::: "memory")
#define CP_WAIT4()  asm volatile("cp.async.wait_group 4;" ::: "memory")

__device__ __forceinline__ void ldsm4(uint32_t* r, uint32_t addr) {
    asm volatile("ldmatrix.sync.aligned.m8n8.x4.shared.b16 {%0,%1,%2,%3}, [%4];"
                 : "=r"(r[0]), "=r"(r[1]), "=r"(r[2]), "=r"(r[3]) : "r"(addr));
}

__device__ __forceinline__ void mma16816(float* d, const uint32_t* a, const uint32_t* b) {
    asm volatile(
        "mma.sync.aligned.m16n8k16.row.col.f32.f16.f16.f32 "
        "{%0,%1,%2,%3}, {%4,%5,%6,%7}, {%8,%9}, {%0,%1,%2,%3};"
        : "+f"(d[0]), "+f"(d[1]), "+f"(d[2]), "+f"(d[3])
        : "r"(a[0]), "r"(a[1]), "r"(a[2]), "r"(a[3]), "r"(b[0]), "r"(b[1]));
}

// swizzled byte offset inside one 128x32 f16 tile (64B rows, 16B chunks)
__device__ __forceinline__ uint32_t swz(int row, int chunk) {
    return (uint32_t)(row * 64 + ((chunk ^ ((row >> 1) & 3)) << 4));
}

// ---------------- prep kernels ----------------
// tokens fp32 -> fp16 (single rounding). Each thread handles 8 values.
__global__ void __launch_bounds__(256) k_cvt_tok(const float* __restrict__ x) {
    size_t i = ((size_t)blockIdx.x * 256 + threadIdx.x) * 8;
    float4 a = *(const float4*)(x + i);
    float4 b = *(const float4*)(x + i + 4);
    float v[8] = {a.x, a.y, a.z, a.w, b.x, b.y, b.z, b.w};
    __align__(16) __half h[8];
#pragma unroll
    for (int j = 0; j < 8; ++j) h[j] = __float2half_rn(v[j]);
    *(uint4*)(g_Ah + i) = *(uint4*)h;
}

// weight [E][K][N] fp32 -> g_Bh [E][N][K] fp16 (transpose + convert)
__global__ void __launch_bounds__(256) k_cvt_w(const float* __restrict__ w) {
    __shared__ float s[64][65];
    const int e = blockIdx.z;
    const int k0 = blockIdx.y * 64;
    const int n0 = blockIdx.x * 64;
    const int tid = threadIdx.x;
#pragma unroll
    for (int i = 0; i < 4; ++i) {
        int task = tid + i * 256;            // 1024 tasks: 64 k-rows x 16 float4
        int kr = task >> 4;
        int nc = (task & 15) * 4;
        float4 v = *(const float4*)(w + ((size_t)e * CU_K + k0 + kr) * CU_N + n0 + nc);
        s[kr][nc + 0] = v.x; s[kr][nc + 1] = v.y;
        s[kr][nc + 2] = v.z; s[kr][nc + 3] = v.w;
    }
    __syncthreads();
#pragma unroll
    for (int i = 0; i < 2; ++i) {
        int task = tid + i * 256;            // 512 tasks: 64 n-rows x 8 k-octets
        int nr = task >> 3;
        int j = (task & 7) * 8;
        __align__(16) __half h[8];
#pragma unroll
        for (int q = 0; q < 8; ++q) h[q] = __float2half_rn(s[j + q][nr]);
        size_t dst = ((size_t)e * CU_N + n0 + nr) * CU_K + k0 + j;
        *(uint4*)(g_Bh + dst) = *(uint4*)h;
    }
}

// fused histogram + prefix + scatter (single CTA)
__global__ void __launch_bounds__(1024) k_bucket(const int* __restrict__ ids) {
    __shared__ int cnt[CU_E], cur[CU_E];
    const int tid = threadIdx.x;
    if (tid < CU_E) cnt[tid] = 0;
    __syncthreads();
#pragma unroll
    for (int i = 0; i < CU_T / 1024; ++i)
        atomicAdd(&cnt[ids[tid + i * 1024]], 1);
    __syncthreads();
    if (tid == 0) {
        int s = 0;
        for (int e = 0; e < CU_E; ++e) {
            g_cnt[e] = cnt[e];
            g_off[e] = s;
            cur[e] = s;
            s += cnt[e];
        }
    }
    __syncthreads();
#pragma unroll
    for (int i = 0; i < CU_T / 1024; ++i) {
        int t = tid + i * 1024;
        int p = atomicAdd(&cur[ids[t]], 1);
        g_idx[p] = t;
    }
}

// ---------------- grouped GEMM (mma.sync fp16 single-pass) ----------------
__device__ __forceinline__ void issue_stage(uint32_t tiles_base, int stage, int kt,
                                            const int* __restrict__ toks,
                                            size_t bbase, int tid) {
    const int k0 = kt * BK;
    const uint32_t st = tiles_base + stage * STAGE_BYTES;
#pragma unroll
    for (int i = 0; i < 4; ++i) {
        const int task = i * 256 + tid;       // 1024 tasks = 2 mats x 128 rows x 4 chunks
        const int mat = task >> 9;
        const int t = task & 511;
        const int row = t >> 2;
        const int chunk = t & 3;
        const uint32_t dst = st + mat * 8192 + swz(row, chunk);
        const __half* src;
        if (mat == 0)
            src = g_Ah + (size_t)toks[row] * CU_K + k0 + chunk * 8;
        else
            src = g_Bh + bbase + (size_t)row * CU_K + k0 + chunk * 8;
        cp_async16(dst, src);
    }
}

__global__ void __launch_bounds__(256, 2) moe_gemm(float* __restrict__ out) {
    const int e = blockIdx.z;
    const int cnt = g_cnt[e];
    const int m0 = blockIdx.y * BM;
    if (m0 >= cnt) return;
    const int n0 = blockIdx.x * BN;

    extern __shared__ __align__(1024) char smem[];
    const uint32_t sb = smem_u32(smem);
    const uint32_t tiles = sb + SM_TILES;
    const int tid = threadIdx.x;
    const int wid = tid >> 5;
    const int lid = tid & 31;

    int* toks_s = (int*)(smem + SM_TOK);
    if (tid < BM) {
        int lr = m0 + tid;
        toks_s[tid] = (lr < cnt) ? g_idx[g_off[e] + lr] : 0;
    }
    __syncthreads();
    const int* toks = toks_s;
    const size_t bbase = ((size_t)e * CU_N + n0) * CU_K;

    // prologue: prefetch 5 stages
#pragma unroll
    for (int s = 0; s < 5; ++s) {
        issue_stage(tiles, s, s, toks, bbase, tid);
        CP_COMMIT();
    }

    // warp / lane decomposition: warp tile 64x32
    const int wm = (wid & 1) * 64;
    const int wn = (wid >> 1) * 32;
    const int q = lid >> 3;
    const int r = lid & 7;

    float acc[4][4][4];
#pragma unroll
    for (int mi = 0; mi < 4; ++mi)
#pragma unroll
        for (int ni = 0; ni < 4; ++ni)
#pragma unroll
            for (int c = 0; c < 4; ++c) acc[mi][ni][c] = 0.f;

    const int arow_base = wm + ((q & 1) << 3) + r;   // + mi*16
    const int achunk_hi = q >> 1;                    // + ks*2
    const int brow_base = wn + ((q >> 1) << 3) + r;  // + p*16
    const int bchunk_lo = q & 1;                     // + ks*2

    int stage = 0;
    for (int kt = 0; kt < KTILES; ++kt) {
        CP_WAIT4();
        __syncthreads();
        if (kt + 5 < KTILES) {
            int ps = stage + 5;
            if (ps >= NSTAGE) ps -= NSTAGE;
            issue_stage(tiles, ps, kt + 5, toks, bbase, tid);
        }
        CP_COMMIT();

        const uint32_t st = tiles + stage * STAGE_BYTES;
        const uint32_t stAh = st, stBh = st + 8192;

#pragma unroll
        for (int ks = 0; ks < 2; ++ks) {
            uint32_t ah[4][4], bh[2][4];
#pragma unroll
            for (int mi = 0; mi < 4; ++mi) {
                const int row = arow_base + mi * 16;
                ldsm4(ah[mi], stAh + swz(row, ks * 2 + achunk_hi));
            }
#pragma unroll
            for (int p = 0; p < 2; ++p) {
                const int row = brow_base + p * 16;
                ldsm4(bh[p], stBh + swz(row, ks * 2 + bchunk_lo));
            }
#pragma unroll
            for (int mi = 0; mi < 4; ++mi)
#pragma unroll
                for (int ni = 0; ni < 4; ++ni)
                    mma16816(acc[mi][ni], ah[mi], &bh[ni >> 1][(ni & 1) * 2]);
        }
        if (++stage == NSTAGE) stage = 0;
    }

    // epilogue: write accumulators to gathered output rows
    const int g = lid >> 2;
    const int tq = lid & 3;
#pragma unroll
    for (int mi = 0; mi < 4; ++mi) {
        const int lr0 = wm + mi * 16 + g;
        const int lr1 = lr0 + 8;
#pragma unroll
        for (int ni = 0; ni < 4; ++ni) {
            const int col = n0 + wn + ni * 8 + tq * 2;
            if (m0 + lr0 < cnt) {
                float2 v = {acc[mi][ni][0], acc[mi][ni][1]};
                *(float2*)(out + (size_t)toks[lr0] * CU_N + col) = v;
            }
            if (m0 + lr1 < cnt) {
                float2 v = {acc[mi][ni][2], acc[mi][ni][3]};
                *(float2*)(out + (size_t)toks[lr1] * CU_N + col) = v;
            }
        }
    }
}

// ---------------- launch ----------------
extern "C" void kernel_launch(void* const* d_in, const int* in_sizes, int n_in,
                              void* d_out, int out_size) {
    const float* tokens = (const float*)d_in[0];
    const float* weight = (const float*)d_in[1];
    const int*   ids    = (const int*)d_in[2];
    float* out = (float*)d_out;

    cudaFuncSetAttribute(moe_gemm, cudaFuncAttributeMaxDynamicSharedMemorySize, SM_TOTAL);

    // 4 launches; with ~2 harness pre-launches, moe_gemm lands at ncu -s 5
    k_cvt_tok<<<(CU_T * CU_K) / 2048, 256>>>(tokens);
    k_cvt_w<<<dim3(CU_N / 64, CU_K / 64, CU_E), 256>>>(weight);
    k_bucket<<<1, 1024>>>(ids);
    moe_gemm<<<dim3(CU_N / BN, CU_T / BM, CU_E), 256, SM_TOTAL>>>(out);
}

// round 11
// speedup vs baseline: 2.8012x; 1.0633x over previous
#include <cuda_runtime.h>
#include <cuda_fp16.h>
#include <cstdint>

#define CU_T 8192
#define CU_K 2048
#define CU_N 2048
#define CU_E 8

#define BM 128
#define BN 128
#define BK 64
#define KTILES (CU_K / BK)      // 32
#define NSTAGE 3
#define STAGE_BYTES 32768       // Ah(16K)+Bh(16K), 128B rows
#define SM_TOK 0                // 128 ints
#define SM_TILES 1024
#define SM_TOTAL (SM_TILES + NSTAGE * STAGE_BYTES)   // 99328 (97KB) -> 2 CTAs/SM

// ---------------- scratch (static device globals; no allocation) ----------------
__device__ __half g_Ah[(size_t)CU_T * CU_K];
__device__ __half g_Bh[(size_t)CU_E * CU_N * CU_K];   // [e][n][k] K-major
__device__ int g_cnt[CU_E];
__device__ int g_off[CU_E];
__device__ int g_idx[CU_T];

// ---------------- PTX helpers ----------------
__device__ __forceinline__ uint32_t smem_u32(const void* p) {
    uint32_t a;
    asm("{ .reg .u64 t; cvta.to.shared.u64 t, %1; cvt.u32.u64 %0, t; }"
        : "=r"(a) : "l"(p));
    return a;
}

__device__ __forceinline__ void cp_async16(uint32_t dst, const void* src) {
    asm volatile("cp.async.cg.shared.global [%0], [%1], 16;" :: "r"(dst), "l"(src));
}
#define CP_COMMIT() asm volatile("cp.async.commit_group;" ::: "memory")
#define CP_WAIT1()  asm volatile("cp.async.wait_group 1;" ::: "memory")

__device__ __forceinline__ void ldsm4(uint32_t* r, uint32_t addr) {
    asm volatile("ldmatrix.sync.aligned.m8n8.x4.shared.b16 {%0,%1,%2,%3}, [%4];"
                 : "=r"(r[0]), "=r"(r[1]), "=r"(r[2]), "=r"(r[3]) : "r"(addr));
}

__device__ __forceinline__ void mma16816(float* d, const uint32_t* a, const uint32_t* b) {
    asm volatile(
        "mma.sync.aligned.m16n8k16.row.col.f32.f16.f16.f32 "
        "{%0,%1,%2,%3}, {%4,%5,%6,%7}, {%8,%9}, {%0,%1,%2,%3};"
        : "+f"(d[0]), "+f"(d[1]), "+f"(d[2]), "+f"(d[3])
        : "r"(a[0]), "r"(a[1]), "r"(a[2]), "r"(a[3]), "r"(b[0]), "r"(b[1]));
}

// swizzled byte offset inside one 128x64 f16 tile (128B rows, 16B chunks, 8-way XOR)
__device__ __forceinline__ uint32_t swz(int row, int chunk) {
    return (uint32_t)(row * 128 + ((chunk ^ (row & 7)) << 4));
}

// ---------------- prep kernels ----------------
// tokens fp32 -> fp16 (single rounding). Each thread handles 8 values.
__global__ void __launch_bounds__(256) k_cvt_tok(const float* __restrict__ x) {
    size_t i = ((size_t)blockIdx.x * 256 + threadIdx.x) * 8;
    float4 a = *(const float4*)(x + i);
    float4 b = *(const float4*)(x + i + 4);
    float v[8] = {a.x, a.y, a.z, a.w, b.x, b.y, b.z, b.w};
    __align__(16) __half h[8];
#pragma unroll
    for (int j = 0; j < 8; ++j) h[j] = __float2half_rn(v[j]);
    *(uint4*)(g_Ah + i) = *(uint4*)h;
}

// weight [E][K][N] fp32 -> g_Bh [E][N][K] fp16 (transpose + convert)
__global__ void __launch_bounds__(256) k_cvt_w(const float* __restrict__ w) {
    __shared__ float s[64][65];
    const int e = blockIdx.z;
    const int k0 = blockIdx.y * 64;
    const int n0 = blockIdx.x * 64;
    const int tid = threadIdx.x;
#pragma unroll
    for (int i = 0; i < 4; ++i) {
        int task = tid + i * 256;            // 1024 tasks: 64 k-rows x 16 float4
        int kr = task >> 4;
        int nc = (task & 15) * 4;
        float4 v = *(const float4*)(w + ((size_t)e * CU_K + k0 + kr) * CU_N + n0 + nc);
        s[kr][nc + 0] = v.x; s[kr][nc + 1] = v.y;
        s[kr][nc + 2] = v.z; s[kr][nc + 3] = v.w;
    }
    __syncthreads();
#pragma unroll
    for (int i = 0; i < 2; ++i) {
        int task = tid + i * 256;            // 512 tasks: 64 n-rows x 8 k-octets
        int nr = task >> 3;
        int j = (task & 7) * 8;
        __align__(16) __half h[8];
#pragma unroll
        for (int q = 0; q < 8; ++q) h[q] = __float2half_rn(s[j + q][nr]);
        size_t dst = ((size_t)e * CU_N + n0 + nr) * CU_K + k0 + j;
        *(uint4*)(g_Bh + dst) = *(uint4*)h;
    }
}

// fused histogram + prefix + scatter (single CTA)
__global__ void __launch_bounds__(1024) k_bucket(const int* __restrict__ ids) {
    __shared__ int cnt[CU_E], cur[CU_E];
    const int tid = threadIdx.x;
    if (tid < CU_E) cnt[tid] = 0;
    __syncthreads();
#pragma unroll
    for (int i = 0; i < CU_T / 1024; ++i)
        atomicAdd(&cnt[ids[tid + i * 1024]], 1);
    __syncthreads();
    if (tid == 0) {
        int s = 0;
        for (int e = 0; e < CU_E; ++e) {
            g_cnt[e] = cnt[e];
            g_off[e] = s;
            cur[e] = s;
            s += cnt[e];
        }
    }
    __syncthreads();
#pragma unroll
    for (int i = 0; i < CU_T / 1024; ++i) {
        int t = tid + i * 1024;
        int p = atomicAdd(&cur[ids[t]], 1);
        g_idx[p] = t;
    }
}

// ---------------- grouped GEMM (mma.sync fp16, BK=64 stages) ----------------
__device__ __forceinline__ void issue_stage(uint32_t tiles_base, int stage, int kt,
                                            const int* __restrict__ toks,
                                            size_t bbase, int tid) {
    const int k0 = kt * BK;
    const uint32_t st = tiles_base + stage * STAGE_BYTES;
#pragma unroll
    for (int i = 0; i < 8; ++i) {
        const int task = i * 256 + tid;       // 2048 tasks = 2 mats x 128 rows x 8 chunks
        const int mat = task >> 10;
        const int t = task & 1023;
        const int row = t >> 3;
        const int chunk = t & 7;
        const uint32_t dst = st + mat * 16384 + swz(row, chunk);
        const __half* src;
        if (mat == 0)
            src = g_Ah + (size_t)toks[row] * CU_K + k0 + chunk * 8;
        else
            src = g_Bh + bbase + (size_t)row * CU_K + k0 + chunk * 8;
        cp_async16(dst, src);
    }
}

__global__ void __launch_bounds__(256, 2) moe_gemm(float* __restrict__ out) {
    const int e = blockIdx.z;
    const int cnt = g_cnt[e];
    const int m0 = blockIdx.y * BM;
    if (m0 >= cnt) return;
    const int n0 = blockIdx.x * BN;

    extern __shared__ __align__(1024) char smem[];
    const uint32_t sb = smem_u32(smem);
    const uint32_t tiles = sb + SM_TILES;
    const int tid = threadIdx.x;
    const int wid = tid >> 5;
    const int lid = tid & 31;

    int* toks_s = (int*)(smem + SM_TOK);
    if (tid < BM) {
        int lr = m0 + tid;
        toks_s[tid] = (lr < cnt) ? g_idx[g_off[e] + lr] : 0;
    }
    __syncthreads();
    const int* toks = toks_s;
    const size_t bbase = ((size_t)e * CU_N + n0) * CU_K;

    // prologue: prefetch 2 stages
#pragma unroll
    for (int s = 0; s < 2; ++s) {
        issue_stage(tiles, s, s, toks, bbase, tid);
        CP_COMMIT();
    }

    // warp / lane decomposition: warp tile 64x32
    const int wm = (wid & 1) * 64;
    const int wn = (wid >> 1) * 32;
    const int q = lid >> 3;
    const int r = lid & 7;

    float acc[4][4][4];
#pragma unroll
    for (int mi = 0; mi < 4; ++mi)
#pragma unroll
        for (int ni = 0; ni < 4; ++ni)
#pragma unroll
            for (int c = 0; c < 4; ++c) acc[mi][ni][c] = 0.f;

    const int arow_base = wm + ((q & 1) << 3) + r;   // + mi*16
    const int achunk_hi = q >> 1;                    // + ks*2
    const int brow_base = wn + ((q >> 1) << 3) + r;  // + p*16
    const int bchunk_lo = q & 1;                     // + ks*2

    int stage = 0;
    for (int kt = 0; kt < KTILES; ++kt) {
        CP_WAIT1();
        __syncthreads();
        if (kt + 2 < KTILES) {
            int ps = stage + 2;
            if (ps >= NSTAGE) ps -= NSTAGE;
            issue_stage(tiles, ps, kt + 2, toks, bbase, tid);
        }
        CP_COMMIT();

        const uint32_t st = tiles + stage * STAGE_BYTES;
        const uint32_t stAh = st, stBh = st + 16384;

#pragma unroll
        for (int ks = 0; ks < 4; ++ks) {
            uint32_t ah[4][4], bh[2][4];
#pragma unroll
            for (int mi = 0; mi < 4; ++mi) {
                const int row = arow_base + mi * 16;
                ldsm4(ah[mi], stAh + swz(row, ks * 2 + achunk_hi));
            }
#pragma unroll
            for (int p = 0; p < 2; ++p) {
                const int row = brow_base + p * 16;
                ldsm4(bh[p], stBh + swz(row, ks * 2 + bchunk_lo));
            }
#pragma unroll
            for (int mi = 0; mi < 4; ++mi)
#pragma unroll
                for (int ni = 0; ni < 4; ++ni)
                    mma16816(acc[mi][ni], ah[mi], &bh[ni >> 1][(ni & 1) * 2]);
        }
        if (++stage == NSTAGE) stage = 0;
    }

    // epilogue: write accumulators to gathered output rows
    const int g = lid >> 2;
    const int tq = lid & 3;
#pragma unroll
    for (int mi = 0; mi < 4; ++mi) {
        const int lr0 = wm + mi * 16 + g;
        const int lr1 = lr0 + 8;
#pragma unroll
        for (int ni = 0; ni < 4; ++ni) {
            const int col = n0 + wn + ni * 8 + tq * 2;
            if (m0 + lr0 < cnt) {
                float2 v = {acc[mi][ni][0], acc[mi][ni][1]};
                *(float2*)(out + (size_t)toks[lr0] * CU_N + col) = v;
            }
            if (m0 + lr1 < cnt) {
                float2 v = {acc[mi][ni][2], acc[mi][ni][3]};
                *(float2*)(out + (size_t)toks[lr1] * CU_N + col) = v;
            }
        }
    }
}

// ---------------- launch ----------------
extern "C" void kernel_launch(void* const* d_in, const int* in_sizes, int n_in,
                              void* d_out, int out_size) {
    const float* tokens = (const float*)d_in[0];
    const float* weight = (const float*)d_in[1];
    const int*   ids    = (const int*)d_in[2];
    float* out = (float*)d_out;

    cudaFuncSetAttribute(moe_gemm, cudaFuncAttributeMaxDynamicSharedMemorySize, SM_TOTAL);

    // 4 launches; moe_gemm observable at ncu -s 5 (confirmed in round 10)
    k_cvt_tok<<<(CU_T * CU_K) / 2048, 256>>>(tokens);
    k_cvt_w<<<dim3(CU_N / 64, CU_K / 64, CU_E), 256>>>(weight);
    k_bucket<<<1, 1024>>>(ids);
    moe_gemm<<<dim3(CU_N / BN, CU_T / BM, CU_E), 256, SM_TOTAL>>>(out);
}